// round 8
// baseline (speedup 1.0000x reference)
#include <cuda_runtime.h>
#include <cuda_bf16.h>
#include <math.h>
#include <float.h>

// ---------------------------------------------------------------------------
// Self_Correlation_Per_tt : x[8,64,64,64] fp32 -> out[8,115,24,24] fp32
// Stage 1: lag-product sliding box sums; 512 threads (row halves paired via
// shfl) for 4 warps/SMSP. Stage 2: c-major pool, register bitonic sort.
// ---------------------------------------------------------------------------

#define IMS 68          // s_img stride
#define CMS 65          // s_corr stride
#define RMS 121         // R row stride
#define N_BC 512        // 8 * 64
#define NP 3249         // 57*57 patch positions
#define POOL_P 576      // 9*64
#define OUT_R 115

#define OFF_IMG  0
#define OFF_CORR (64 * IMS)
#define OFF_R    (OFF_CORR + 64 * CMS)
#define S1_SMEM_FLOATS (OFF_R + 4 * 64 * RMS)
#define S1_SMEM_BYTES  (S1_SMEM_FLOATS * 4)

// c-major: [b][c][p]
__device__ __align__(16) float g_pool2t[8 * 64 * POOL_P];
__device__ float g_invn[8 * POOL_P];

// XOR bank swizzle for 1024-grid indices
__device__ __forceinline__ int ph(int i) {
    return (i & ~31) | ((i ^ (i >> 5)) & 31);
}

// ---------------------------------------------------------------------------
// Stage 1: one block per (b,c). 512 threads, 154KB dynamic smem.
// Thread (g, u, h): di group g, image row u, v-half h. Lane pairs (2i,2i+1)
// hold the two halves; window sums combine with shfl_xor(.,1).
// ---------------------------------------------------------------------------
__global__ __launch_bounds__(512) void stage1_kernel(const float* __restrict__ x)
{
    extern __shared__ float smem[];
    float* s_img  = smem + OFF_IMG;
    float* s_corr = smem + OFF_CORR;
    float* s_R    = smem + OFF_R;
    __shared__ float s_norm[64];

    const int tid = threadIdx.x;
    const int blk = blockIdx.x;        // b*64 + c
    const int bb  = blk >> 6;
    const int cc  = blk & 63;

    const float* src = x + (size_t)blk * 4096;
    for (int i = tid; i < 4096; i += 512)
        s_img[(i >> 6) * IMS + (i & 63)] = src[i];
    __syncthreads();

    const int g = tid >> 7;            // di group 0..3
    const int u = (tid >> 1) & 63;     // image row
    const int h = tid & 1;             // v-half

    for (int rnd = 0; rnd < 2; ++rnd) {
        const int di   = rnd * 4 + g;
        const int rowB = (u + di <= 63) ? (u + di) : 63;   // clamp (inactive)
        const bool act = (u + di <= 63);

        // ---- phase A ------------------------------------------------------
        // ra: 32 floats = cols [h*32, h*32+32) of row u
        float ra[32];
        {
            const float4* pA = (const float4*)(s_img + u * IMS + h * 32);
#pragma unroll
            for (int t = 0; t < 8; ++t) {
                float4 v = pA[t];
                ra[4*t+0] = v.x; ra[4*t+1] = v.y; ra[4*t+2] = v.z; ra[4*t+3] = v.w;
            }
        }
        // rbx: zero-padded window of row u+di; index semantics:
        //   h=0: rbx[idx] = col (idx-7)   (cols -7..40 ; <0 zeroed)
        //   h=1: rbx[idx] = col (idx+25)  (cols 25..72 ; >63 zeroed)
        // In both cases the main dot is  sum_w ra[w]*rbx[w+dj+7].
        float rbx[48];
#pragma unroll
        for (int i = 0; i < 48; ++i) rbx[i] = 0.0f;
        if (h == 0) {
            const float4* pB = (const float4*)(s_img + rowB * IMS);   // col 0
#pragma unroll
            for (int t = 0; t < 10; ++t) {
                float4 v = pB[t];
                rbx[7+4*t] = v.x; rbx[8+4*t] = v.y;
                rbx[9+4*t] = v.z; rbx[10+4*t] = v.w;
            }
        } else {
            const float4* pB = (const float4*)(s_img + rowB * IMS + 24); // col 24
            {
                float4 v = pB[0];                 // cols 24..27 -> idx -1..2
                rbx[0] = v.y; rbx[1] = v.z; rbx[2] = v.w;
            }
#pragma unroll
            for (int t = 1; t < 10; ++t) {
                float4 v = pB[t];                 // cols 24+4t -> idx 4t-1
                rbx[4*t-1] = v.x; rbx[4*t+0] = v.y;
                rbx[4*t+1] = v.z; rbx[4*t+2] = v.w;
            }
        }

        float* Rrow = s_R + (g * 64 + u) * RMS;

#pragma unroll
        for (int dj = -7; dj <= 7; ++dj) {
            const int bl = (dj < 0) ? -dj : 0;
            const int bh = (dj > 0) ? 7 - dj : 7;

            // unified half dot (zero padding handles boundaries)
            float ac0 = 0.f, ac1 = 0.f, ac2 = 0.f, ac3 = 0.f;
#pragma unroll
            for (int w2 = 0; w2 < 32; w2 += 4) {
                ac0 = fmaf(ra[w2+0], rbx[w2+dj+7],  ac0);
                ac1 = fmaf(ra[w2+1], rbx[w2+dj+8],  ac1);
                ac2 = fmaf(ra[w2+2], rbx[w2+dj+9],  ac2);
                ac3 = fmaf(ra[w2+3], rbx[w2+dj+10], ac3);
            }
            const float base = (ac0 + ac2) + (ac1 + ac3);

            float part[8];
            if (h == 0) {
                // part[k] = sum_{v=k}^{31} prod  (suffix, shrink from below)
                part[0] = base;
#pragma unroll
                for (int k = 1; k <= 7; ++k)
                    part[k] = part[k-1] - ra[k-1] * rbx[k-1+dj+7];
            } else {
                // part[k] = sum_{v=32}^{k+56} prod (prefix, shrink from above)
                part[7] = base;
#pragma unroll
                for (int k = 6; k >= 0; --k)
                    part[k] = part[k+1] - ra[k+25] * rbx[k+dj+32];
            }

#pragma unroll
            for (int k = bl; k <= bh; ++k) {
                float Rv = part[k] + __shfl_xor_sync(0xffffffffu, part[k], 1);
                if (h == 0 && act)
                    Rrow[(dj + 7) * 8 + k] = Rv;
            }
        }
        __syncthreads();

        // ---- phase B: vertical sliding sums (480 tasks, 1/thread) --------
        if (tid < 480) {
            const int g2  = tid / 120;
            const int rem = tid % 120;
            const int dj  = rem / 8 - 7;
            const int b2  = rem % 8;
            const int di2 = rnd * 4 + g2;
            const int bl  = (dj < 0) ? -dj : 0;
            const int bh  = (dj > 0) ? 7 - dj : 7;
            if (b2 >= bl && b2 <= bh && !(di2 == 0 && dj < 0)) {
                const float* Rcol = s_R + g2 * 64 * RMS + rem;
                float a0 = 0.f, a1 = 0.f, a2 = 0.f, a3 = 0.f;
#pragma unroll
                for (int uu = 0; uu < 56; uu += 4) {
                    a0 += Rcol[(uu    ) * RMS];
                    a1 += Rcol[(uu + 1) * RMS];
                    a2 += Rcol[(uu + 2) * RMS];
                    a3 += Rcol[(uu + 3) * RMS];
                }
                float acc = ((a0 + a2) + (a1 + a3)) + Rcol[56 * RMS];
                int m = b2;
                int n = di2 * 8 + (b2 + dj);
                s_corr[m * CMS + n] = acc;
                s_corr[n * CMS + m] = acc;
#pragma unroll
                for (int a = 1; a <= 7; ++a) {
                    if (a <= 7 - di2) {
                        acc += Rcol[(a + 56) * RMS] - Rcol[(a - 1) * RMS];
                        m = a * 8 + b2;
                        n = (a + di2) * 8 + (b2 + dj);
                        s_corr[m * CMS + n] = acc;
                        s_corr[n * CMS + m] = acc;
                    }
                }
            }
        }
        __syncthreads();
    }

    // ---- norms from the raw diagonal -------------------------------------
    if (tid < 64) {
        float gdiag = s_corr[tid * CMS + tid];
        s_norm[tid] = 1.0f / fmaxf(sqrtf(gdiag), 1e-12f);
    }
    __syncthreads();

    // ---- ranking: warp w bitonic-sorts columns w*4..w*4+3 (64 vals each) --
    {
        const int lane = tid & 31;
        const int w    = tid >> 5;            // 0..15
        float* dstc = g_pool2t + (size_t)(bb * 64 + cc) * POOL_P;
        const float invP = 1.0f / (float)NP;
        const float nm0 = s_norm[lane] * invP;
        const float nm1 = s_norm[lane + 32] * invP;

        float v0[4], v1[4];
#pragma unroll
        for (int ci = 0; ci < 4; ++ci) {
            const int n = w * 4 + ci;
            const float sn = s_norm[n];
            v0[ci] = s_corr[lane * CMS + n] * nm0 * sn;          // i = lane
            v1[ci] = s_corr[(lane + 32) * CMS + n] * nm1 * sn;   // i = lane+32
        }

        // bitonic sort descending over i = lane + 32*r
#pragma unroll
        for (int s = 1; s <= 5; ++s) {
            const int kk = 1 << s;
#pragma unroll
            for (int j = (1 << (s - 1)); j >= 1; j >>= 1) {
#pragma unroll
                for (int ci = 0; ci < 4; ++ci) {
                    const bool A = ((lane & j) == 0);
                    bool d0, d1;
                    if (s < 5) { d0 = ((lane & kk) == 0); d1 = d0; }
                    else       { d0 = true; d1 = false; }
                    float p0 = __shfl_xor_sync(0xffffffffu, v0[ci], j);
                    v0[ci] = ((d0 == A) ? fmaxf(v0[ci], p0) : fminf(v0[ci], p0));
                    float p1 = __shfl_xor_sync(0xffffffffu, v1[ci], j);
                    v1[ci] = ((d1 == A) ? fmaxf(v1[ci], p1) : fminf(v1[ci], p1));
                }
            }
        }
        // stage s=6: j=32 cross-register step
#pragma unroll
        for (int ci = 0; ci < 4; ++ci) {
            float hi = fmaxf(v0[ci], v1[ci]);
            float lo = fminf(v0[ci], v1[ci]);
            v0[ci] = hi; v1[ci] = lo;
        }
#pragma unroll
        for (int j = 16; j >= 1; j >>= 1) {
#pragma unroll
            for (int ci = 0; ci < 4; ++ci) {
                const bool A = ((lane & j) == 0);
                float p0 = __shfl_xor_sync(0xffffffffu, v0[ci], j);
                v0[ci] = A ? fmaxf(v0[ci], p0) : fminf(v0[ci], p0);
                float p1 = __shfl_xor_sync(0xffffffffu, v1[ci], j);
                v1[ci] = A ? fmaxf(v1[ci], p1) : fminf(v1[ci], p1);
            }
        }

        // emit ranks {1,9,16,24} from v0 (i=lane), {32,40,48,55,63} from v1
#pragma unroll
        for (int ci = 0; ci < 4; ++ci) {
            const int n = w * 4 + ci;
            if (lane == 1)  dstc[0 * 64 + n] = v0[ci];
            if (lane == 9)  dstc[1 * 64 + n] = v0[ci];
            if (lane == 16) dstc[2 * 64 + n] = v0[ci];
            if (lane == 24) dstc[3 * 64 + n] = v0[ci];
            if (lane == 0)  dstc[4 * 64 + n] = v1[ci];
            if (lane == 8)  dstc[5 * 64 + n] = v1[ci];
            if (lane == 16) dstc[6 * 64 + n] = v1[ci];
            if (lane == 23) dstc[7 * 64 + n] = v1[ci];
            if (lane == 31) dstc[8 * 64 + n] = v1[ci];
        }
    }
}

// ---------------------------------------------------------------------------
// Stage 2a: per-(b,p) inverse norms over c (coalesced over p).
// ---------------------------------------------------------------------------
__global__ void invn_kernel()
{
    int idx = blockIdx.x * blockDim.x + threadIdx.x;
    if (idx >= 8 * POOL_P) return;
    const int b = idx / POOL_P, p = idx % POOL_P;
    const float* base = g_pool2t + (size_t)b * 64 * POOL_P + p;
    float s0 = 0.f, s1 = 0.f, s2 = 0.f, s3 = 0.f;
#pragma unroll
    for (int c = 0; c < 64; c += 4) {
        float x0 = base[(c    ) * POOL_P];
        float x1 = base[(c + 1) * POOL_P];
        float x2 = base[(c + 2) * POOL_P];
        float x3 = base[(c + 3) * POOL_P];
        s0 = fmaf(x0, x0, s0); s1 = fmaf(x1, x1, s1);
        s2 = fmaf(x2, x2, s2); s3 = fmaf(x3, x3, s3);
    }
    float s = (s0 + s2) + (s1 + s3);
    g_invn[idx] = 1.0f / fmaxf(sqrtf(s), 1e-12f);
}

// ---------------------------------------------------------------------------
// Bitonic steps, layout i = lane*32 + r (compile-time register indices).
// ---------------------------------------------------------------------------
template<int S, int JJ>
__device__ __forceinline__ void bstep_reg(float (&val)[32], int lane)
{
    constexpr int J = 1 << JJ;            // JJ <= 4
    bool dsc_rt = true;
    if (S >= 5 && S <= 9) dsc_rt = ((lane & (1 << (S - 5))) == 0);
#pragma unroll
    for (int r = 0; r < 32; ++r) {
        if ((r & J) == 0) {
            const int rp = r | J;
            bool dsc;
            if (S <= 4) dsc = ((r & (1 << S)) == 0);
            else        dsc = dsc_rt;
            float hi = fmaxf(val[r], val[rp]);
            float lo = fminf(val[r], val[rp]);
            val[r]  = dsc ? hi : lo;
            val[rp] = dsc ? lo : hi;
        }
    }
}

template<int S, int JJ>
__device__ __forceinline__ void bstep_shfl(float (&val)[32], int lane)
{
    constexpr int L = 1 << (JJ - 5);      // JJ >= 5, S >= 6
    const bool A = ((lane & L) == 0);
    bool dsc = true;
    if (S <= 9) dsc = ((lane & (1 << (S - 5))) == 0);
    const bool keep_max = (dsc == A);
#pragma unroll
    for (int r = 0; r < 32; ++r) {
        float pv = __shfl_xor_sync(0xffffffffu, val[r], L);
        val[r] = keep_max ? fmaxf(val[r], pv) : fminf(val[r], pv);
    }
}

// ---------------------------------------------------------------------------
// Stage 2b: one block per (b, 8 q). Warp w sorts column q0+w.
// ---------------------------------------------------------------------------
__global__ __launch_bounds__(256) void stage2_kernel(float* __restrict__ out)
{
    __shared__ float4 s_xq4[8][16];          // 8 q vectors x 64 ch
    __shared__ float  s_cols[8][POOL_P];     // swizzled via ph()

    const int tid  = threadIdx.x;
    const int lane = tid & 31;
    const int w    = tid >> 5;
    const int b    = blockIdx.x / 72;
    const int q0   = (blockIdx.x % 72) * 8;

    const float* poolb = g_pool2t + (size_t)b * 64 * POOL_P;

    {   // load 8 q vectors
        float* sx = (float*)s_xq4;
        for (int i = tid; i < 512; i += 256) {
            int k = i >> 6, c = i & 63;
            sx[k * 64 + c] = poolb[(size_t)c * POOL_P + (q0 + k)];
        }
    }
    __syncthreads();

    // ---- dot phase: thread handles p = tid, tid+256, tid+512 -------------
    {
        float d[3][8];
#pragma unroll
        for (int pi = 0; pi < 3; ++pi)
#pragma unroll
            for (int k = 0; k < 8; ++k) d[pi][k] = 0.0f;

#pragma unroll 4
        for (int c4 = 0; c4 < 16; ++c4) {
            float4 q[8];
#pragma unroll
            for (int k = 0; k < 8; ++k) q[k] = s_xq4[k][c4];
            const float* xb = poolb + (size_t)(c4 * 4) * POOL_P;
#pragma unroll
            for (int pi = 0; pi < 3; ++pi) {
                const int p = tid + pi * 256;
                if (p < POOL_P) {
                    float x0 = xb[p];
                    float x1 = xb[POOL_P + p];
                    float x2 = xb[2 * POOL_P + p];
                    float x3 = xb[3 * POOL_P + p];
#pragma unroll
                    for (int k = 0; k < 8; ++k) {
                        d[pi][k] = fmaf(x0, q[k].x, d[pi][k]);
                        d[pi][k] = fmaf(x1, q[k].y, d[pi][k]);
                        d[pi][k] = fmaf(x2, q[k].z, d[pi][k]);
                        d[pi][k] = fmaf(x3, q[k].w, d[pi][k]);
                    }
                }
            }
        }
#pragma unroll
        for (int pi = 0; pi < 3; ++pi) {
            const int p = tid + pi * 256;
            if (p < POOL_P) {
                const float ip = g_invn[b * POOL_P + p];
                const int pp = ph(p);
#pragma unroll
                for (int k = 0; k < 8; ++k)
                    s_cols[k][pp] = d[pi][k] * ip;
            }
        }
    }
    __syncthreads();

    // ---- register bitonic sort, i = lane*32 + r; conflict-free loads -----
    float val[32];
#pragma unroll
    for (int r = 0; r < 32; ++r)
        val[r] = (lane < 18) ? s_cols[w][lane * 32 + ((r ^ lane) & 31)]
                             : -FLT_MAX;

    bstep_reg<1,0>(val, lane);
    bstep_reg<2,1>(val, lane); bstep_reg<2,0>(val, lane);
    bstep_reg<3,2>(val, lane); bstep_reg<3,1>(val, lane); bstep_reg<3,0>(val, lane);
    bstep_reg<4,3>(val, lane); bstep_reg<4,2>(val, lane); bstep_reg<4,1>(val, lane); bstep_reg<4,0>(val, lane);
    bstep_reg<5,4>(val, lane); bstep_reg<5,3>(val, lane); bstep_reg<5,2>(val, lane); bstep_reg<5,1>(val, lane); bstep_reg<5,0>(val, lane);
    bstep_shfl<6,5>(val, lane);
    bstep_reg<6,4>(val, lane); bstep_reg<6,3>(val, lane); bstep_reg<6,2>(val, lane); bstep_reg<6,1>(val, lane); bstep_reg<6,0>(val, lane);
    bstep_shfl<7,6>(val, lane); bstep_shfl<7,5>(val, lane);
    bstep_reg<7,4>(val, lane); bstep_reg<7,3>(val, lane); bstep_reg<7,2>(val, lane); bstep_reg<7,1>(val, lane); bstep_reg<7,0>(val, lane);
    bstep_shfl<8,7>(val, lane); bstep_shfl<8,6>(val, lane); bstep_shfl<8,5>(val, lane);
    bstep_reg<8,4>(val, lane); bstep_reg<8,3>(val, lane); bstep_reg<8,2>(val, lane); bstep_reg<8,1>(val, lane); bstep_reg<8,0>(val, lane);
    bstep_shfl<9,8>(val, lane); bstep_shfl<9,7>(val, lane); bstep_shfl<9,6>(val, lane); bstep_shfl<9,5>(val, lane);
    bstep_reg<9,4>(val, lane); bstep_reg<9,3>(val, lane); bstep_reg<9,2>(val, lane); bstep_reg<9,1>(val, lane); bstep_reg<9,0>(val, lane);
    bstep_shfl<10,9>(val, lane); bstep_shfl<10,8>(val, lane); bstep_shfl<10,7>(val, lane); bstep_shfl<10,6>(val, lane); bstep_shfl<10,5>(val, lane);
    bstep_reg<10,4>(val, lane); bstep_reg<10,3>(val, lane); bstep_reg<10,2>(val, lane); bstep_reg<10,1>(val, lane); bstep_reg<10,0>(val, lane);

    if (lane < 18) {
#pragma unroll
        for (int r = 0; r < 32; ++r)
            s_cols[w][lane * 32 + ((r ^ lane) & 31)] = val[r];
    }
    __syncthreads();

    const double step = 574.0 / 114.0;   // np.linspace(1, 575, 115) step
    for (int idx = tid; idx < 8 * OUT_R; idx += 256) {
        int k = idx & 7, rr = idx >> 3;
        int rank = (int)rint(1.0 + (double)rr * step);  // half-even == np.round
        float invq = g_invn[b * POOL_P + q0 + k];
        out[((size_t)b * OUT_R + rr) * POOL_P + (q0 + k)] =
            s_cols[k][ph(rank)] * invq * (1.0f / 64.0f);
    }
}

// ---------------------------------------------------------------------------
extern "C" void kernel_launch(void* const* d_in, const int* in_sizes, int n_in,
                              void* d_out, int out_size)
{
    const float* x = (const float*)d_in[0];
    float* out = (float*)d_out;

    cudaFuncSetAttribute(stage1_kernel,
                         cudaFuncAttributeMaxDynamicSharedMemorySize,
                         S1_SMEM_BYTES);
    stage1_kernel<<<N_BC, 512, S1_SMEM_BYTES>>>(x);
    invn_kernel<<<(8 * POOL_P + 255) / 256, 256>>>();
    stage2_kernel<<<8 * 72, 256>>>(out);
}

// round 9
// speedup vs baseline: 1.0912x; 1.0912x over previous
#include <cuda_runtime.h>
#include <cuda_bf16.h>
#include <math.h>
#include <float.h>

// ---------------------------------------------------------------------------
// Self_Correlation_Per_tt : x[8,64,64,64] fp32 -> out[8,115,24,24] fp32
// Stage 1 split: s1a (per (b,c,di): phase A + phase B -> global G scatter),
// s1b (per (b,c): norms + warp-sort ranking). Stage 2 unchanged.
// ---------------------------------------------------------------------------

#define IMS 68          // s_img stride
#define CMS 65          // s_corr stride
#define RMS 121         // R row stride
#define NP 3249         // 57*57 patch positions
#define POOL_P 576      // 9*64
#define OUT_R 115

#define S1A_SMEM_FLOATS (64 * IMS + 64 * RMS)
#define S1A_SMEM_BYTES  (S1A_SMEM_FLOATS * 4)

__device__ __align__(16) float g_corr[512 * 4096];          // [bc][m*64+n]
__device__ __align__(16) float g_pool2t[8 * 64 * POOL_P];   // [b][c][p]
__device__ float g_invn[8 * POOL_P];

// XOR bank swizzle for 1024-grid indices
__device__ __forceinline__ int ph(int i) {
    return (i & ~31) | ((i ^ (i >> 5)) & 31);
}

// ---------------------------------------------------------------------------
// Stage 1a: one block per (bc, di). 128 threads = 64 rows x 2 halves.
// ---------------------------------------------------------------------------
__global__ __launch_bounds__(128) void s1a_kernel(const float* __restrict__ x)
{
    extern __shared__ float smem[];
    float* s_img = smem;               // [64][IMS]
    float* s_R   = smem + 64 * IMS;    // [64][RMS]

    const int tid = threadIdx.x;
    const int blk = blockIdx.x;
    const int bc  = blk >> 3;
    const int di  = blk & 7;

    const float* src = x + (size_t)bc * 4096;
    for (int i = tid; i < 4096; i += 128)
        s_img[(i >> 6) * IMS + (i & 63)] = src[i];
    __syncthreads();

    const int u = tid >> 1;            // image row
    const int h = tid & 1;             // v-half
    const bool act = (u + di <= 63);
    const int rowB = act ? (u + di) : 63;

    // ---- phase A: half-row sliding sums (paired lanes combine via shfl) --
    float ra[32];
    {
        const float4* pA = (const float4*)(s_img + u * IMS + h * 32);
#pragma unroll
        for (int t = 0; t < 8; ++t) {
            float4 v = pA[t];
            ra[4*t+0] = v.x; ra[4*t+1] = v.y; ra[4*t+2] = v.z; ra[4*t+3] = v.w;
        }
    }
    // rbx: zero-padded window of row u+di:
    //   h=0: rbx[idx] = col (idx-7)   (cols -7..40)
    //   h=1: rbx[idx] = col (idx+25)  (cols 25..72)
    float rbx[48];
#pragma unroll
    for (int i = 0; i < 48; ++i) rbx[i] = 0.0f;
    if (h == 0) {
        const float4* pB = (const float4*)(s_img + rowB * IMS);
#pragma unroll
        for (int t = 0; t < 10; ++t) {
            float4 v = pB[t];
            rbx[7+4*t] = v.x; rbx[8+4*t] = v.y;
            rbx[9+4*t] = v.z; rbx[10+4*t] = v.w;
        }
    } else {
        const float4* pB = (const float4*)(s_img + rowB * IMS + 24);
        {
            float4 v = pB[0];
            rbx[0] = v.y; rbx[1] = v.z; rbx[2] = v.w;
        }
#pragma unroll
        for (int t = 1; t < 10; ++t) {
            float4 v = pB[t];
            rbx[4*t-1] = v.x; rbx[4*t+0] = v.y;
            rbx[4*t+1] = v.z; rbx[4*t+2] = v.w;
        }
    }

    float* Rrow = s_R + u * RMS;

#pragma unroll
    for (int dj = -7; dj <= 7; ++dj) {
        const int bl = (dj < 0) ? -dj : 0;
        const int bh = (dj > 0) ? 7 - dj : 7;

        float ac0 = 0.f, ac1 = 0.f, ac2 = 0.f, ac3 = 0.f;
#pragma unroll
        for (int w2 = 0; w2 < 32; w2 += 4) {
            ac0 = fmaf(ra[w2+0], rbx[w2+dj+7],  ac0);
            ac1 = fmaf(ra[w2+1], rbx[w2+dj+8],  ac1);
            ac2 = fmaf(ra[w2+2], rbx[w2+dj+9],  ac2);
            ac3 = fmaf(ra[w2+3], rbx[w2+dj+10], ac3);
        }
        const float base = (ac0 + ac2) + (ac1 + ac3);

        float part[8];
        if (h == 0) {
            part[0] = base;
#pragma unroll
            for (int k = 1; k <= 7; ++k)
                part[k] = part[k-1] - ra[k-1] * rbx[k-1+dj+7];
        } else {
            part[7] = base;
#pragma unroll
            for (int k = 6; k >= 0; --k)
                part[k] = part[k+1] - ra[k+25] * rbx[k+dj+32];
        }

#pragma unroll
        for (int k = bl; k <= bh; ++k) {
            float Rv = part[k] + __shfl_xor_sync(0xffffffffu, part[k], 1);
            if (h == 0 && act)
                Rrow[(dj + 7) * 8 + k] = Rv;
        }
    }
    __syncthreads();

    // ---- phase B: 120 vertical sliding-sum tasks for this di -------------
    if (tid < 120) {
        const int dj = tid / 8 - 7;
        const int b2 = tid % 8;
        const int bl = (dj < 0) ? -dj : 0;
        const int bh = (dj > 0) ? 7 - dj : 7;
        if (b2 >= bl && b2 <= bh && !(di == 0 && dj < 0)) {
            const float* Rcol = s_R + tid;
            float a0 = 0.f, a1 = 0.f, a2 = 0.f, a3 = 0.f;
#pragma unroll
            for (int uu = 0; uu < 56; uu += 4) {
                a0 += Rcol[(uu    ) * RMS];
                a1 += Rcol[(uu + 1) * RMS];
                a2 += Rcol[(uu + 2) * RMS];
                a3 += Rcol[(uu + 3) * RMS];
            }
            float acc = ((a0 + a2) + (a1 + a3)) + Rcol[56 * RMS];
            float* gc = g_corr + (size_t)bc * 4096;
            int m = b2;
            int n = di * 8 + (b2 + dj);
            gc[m * 64 + n] = acc;
            gc[n * 64 + m] = acc;
#pragma unroll
            for (int a = 1; a <= 7; ++a) {
                if (a <= 7 - di) {
                    acc += Rcol[(a + 56) * RMS] - Rcol[(a - 1) * RMS];
                    m = a * 8 + b2;
                    n = (a + di) * 8 + (b2 + dj);
                    gc[m * 64 + n] = acc;
                    gc[n * 64 + m] = acc;
                }
            }
        }
    }
}

// ---------------------------------------------------------------------------
// Stage 1b: one block per bc. Norms + warp-sort ranking -> pool (c-major).
// ---------------------------------------------------------------------------
__global__ __launch_bounds__(256) void s1b_kernel()
{
    __shared__ float s_corr[64 * CMS];
    __shared__ float s_norm[64];

    const int tid = threadIdx.x;
    const int bc  = blockIdx.x;
    const int bb  = bc >> 6;
    const int cc  = bc & 63;

    const float* src = g_corr + (size_t)bc * 4096;
    for (int i = tid; i < 4096; i += 256)
        s_corr[(i >> 6) * CMS + (i & 63)] = src[i];
    __syncthreads();

    if (tid < 64) {
        float gdiag = s_corr[tid * CMS + tid];
        s_norm[tid] = 1.0f / fmaxf(sqrtf(gdiag), 1e-12f);
    }
    __syncthreads();

    // warp w bitonic-sorts columns w*8..w*8+7 (64 values each, descending)
    const int lane = tid & 31;
    const int w    = tid >> 5;
    float* dstc = g_pool2t + (size_t)(bb * 64 + cc) * POOL_P;
    const float invP = 1.0f / (float)NP;
    const float nm0 = s_norm[lane] * invP;
    const float nm1 = s_norm[lane + 32] * invP;

    float v0[8], v1[8];
#pragma unroll
    for (int ci = 0; ci < 8; ++ci) {
        const int n = w * 8 + ci;
        const float sn = s_norm[n];
        v0[ci] = s_corr[lane * CMS + n] * nm0 * sn;          // i = lane
        v1[ci] = s_corr[(lane + 32) * CMS + n] * nm1 * sn;   // i = lane+32
    }

#pragma unroll
    for (int s = 1; s <= 5; ++s) {
        const int kk = 1 << s;
#pragma unroll
        for (int j = (1 << (s - 1)); j >= 1; j >>= 1) {
#pragma unroll
            for (int ci = 0; ci < 8; ++ci) {
                const bool A = ((lane & j) == 0);
                bool d0, d1;
                if (s < 5) { d0 = ((lane & kk) == 0); d1 = d0; }
                else       { d0 = true; d1 = false; }
                float p0 = __shfl_xor_sync(0xffffffffu, v0[ci], j);
                v0[ci] = ((d0 == A) ? fmaxf(v0[ci], p0) : fminf(v0[ci], p0));
                float p1 = __shfl_xor_sync(0xffffffffu, v1[ci], j);
                v1[ci] = ((d1 == A) ? fmaxf(v1[ci], p1) : fminf(v1[ci], p1));
            }
        }
    }
#pragma unroll
    for (int ci = 0; ci < 8; ++ci) {
        float hi = fmaxf(v0[ci], v1[ci]);
        float lo = fminf(v0[ci], v1[ci]);
        v0[ci] = hi; v1[ci] = lo;
    }
#pragma unroll
    for (int j = 16; j >= 1; j >>= 1) {
#pragma unroll
        for (int ci = 0; ci < 8; ++ci) {
            const bool A = ((lane & j) == 0);
            float p0 = __shfl_xor_sync(0xffffffffu, v0[ci], j);
            v0[ci] = A ? fmaxf(v0[ci], p0) : fminf(v0[ci], p0);
            float p1 = __shfl_xor_sync(0xffffffffu, v1[ci], j);
            v1[ci] = A ? fmaxf(v1[ci], p1) : fminf(v1[ci], p1);
        }
    }

    // emit ranks {1,9,16,24} from v0 (i=lane), {32,40,48,55,63} from v1
#pragma unroll
    for (int ci = 0; ci < 8; ++ci) {
        const int n = w * 8 + ci;
        if (lane == 1)  dstc[0 * 64 + n] = v0[ci];
        if (lane == 9)  dstc[1 * 64 + n] = v0[ci];
        if (lane == 16) dstc[2 * 64 + n] = v0[ci];
        if (lane == 24) dstc[3 * 64 + n] = v0[ci];
        if (lane == 0)  dstc[4 * 64 + n] = v1[ci];
        if (lane == 8)  dstc[5 * 64 + n] = v1[ci];
        if (lane == 16) dstc[6 * 64 + n] = v1[ci];
        if (lane == 23) dstc[7 * 64 + n] = v1[ci];
        if (lane == 31) dstc[8 * 64 + n] = v1[ci];
    }
}

// ---------------------------------------------------------------------------
// Stage 2a: per-(b,p) inverse norms over c (coalesced over p).
// ---------------------------------------------------------------------------
__global__ void invn_kernel()
{
    int idx = blockIdx.x * blockDim.x + threadIdx.x;
    if (idx >= 8 * POOL_P) return;
    const int b = idx / POOL_P, p = idx % POOL_P;
    const float* base = g_pool2t + (size_t)b * 64 * POOL_P + p;
    float s0 = 0.f, s1 = 0.f, s2 = 0.f, s3 = 0.f;
#pragma unroll
    for (int c = 0; c < 64; c += 4) {
        float x0 = base[(c    ) * POOL_P];
        float x1 = base[(c + 1) * POOL_P];
        float x2 = base[(c + 2) * POOL_P];
        float x3 = base[(c + 3) * POOL_P];
        s0 = fmaf(x0, x0, s0); s1 = fmaf(x1, x1, s1);
        s2 = fmaf(x2, x2, s2); s3 = fmaf(x3, x3, s3);
    }
    float s = (s0 + s2) + (s1 + s3);
    g_invn[idx] = 1.0f / fmaxf(sqrtf(s), 1e-12f);
}

// ---------------------------------------------------------------------------
// Bitonic steps, layout i = lane*32 + r.
// ---------------------------------------------------------------------------
template<int S, int JJ>
__device__ __forceinline__ void bstep_reg(float (&val)[32], int lane)
{
    constexpr int J = 1 << JJ;            // JJ <= 4
    bool dsc_rt = true;
    if (S >= 5 && S <= 9) dsc_rt = ((lane & (1 << (S - 5))) == 0);
#pragma unroll
    for (int r = 0; r < 32; ++r) {
        if ((r & J) == 0) {
            const int rp = r | J;
            bool dsc;
            if (S <= 4) dsc = ((r & (1 << S)) == 0);
            else        dsc = dsc_rt;
            float hi = fmaxf(val[r], val[rp]);
            float lo = fminf(val[r], val[rp]);
            val[r]  = dsc ? hi : lo;
            val[rp] = dsc ? lo : hi;
        }
    }
}

template<int S, int JJ>
__device__ __forceinline__ void bstep_shfl(float (&val)[32], int lane)
{
    constexpr int L = 1 << (JJ - 5);      // JJ >= 5, S >= 6
    const bool A = ((lane & L) == 0);
    bool dsc = true;
    if (S <= 9) dsc = ((lane & (1 << (S - 5))) == 0);
    const bool keep_max = (dsc == A);
#pragma unroll
    for (int r = 0; r < 32; ++r) {
        float pv = __shfl_xor_sync(0xffffffffu, val[r], L);
        val[r] = keep_max ? fmaxf(val[r], pv) : fminf(val[r], pv);
    }
}

// ---------------------------------------------------------------------------
// Stage 2b: one block per (b, 8 q). Warp w sorts column q0+w.
// ---------------------------------------------------------------------------
__global__ __launch_bounds__(256) void stage2_kernel(float* __restrict__ out)
{
    __shared__ float4 s_xq4[8][16];          // 8 q vectors x 64 ch
    __shared__ float  s_cols[8][POOL_P];     // swizzled via ph()

    const int tid  = threadIdx.x;
    const int lane = tid & 31;
    const int w    = tid >> 5;
    const int b    = blockIdx.x / 72;
    const int q0   = (blockIdx.x % 72) * 8;

    const float* poolb = g_pool2t + (size_t)b * 64 * POOL_P;

    {   // load 8 q vectors
        float* sx = (float*)s_xq4;
        for (int i = tid; i < 512; i += 256) {
            int k = i >> 6, c = i & 63;
            sx[k * 64 + c] = poolb[(size_t)c * POOL_P + (q0 + k)];
        }
    }
    __syncthreads();

    // ---- dot phase: thread handles p = tid, tid+256, tid+512 -------------
    {
        float d[3][8];
#pragma unroll
        for (int pi = 0; pi < 3; ++pi)
#pragma unroll
            for (int k = 0; k < 8; ++k) d[pi][k] = 0.0f;

#pragma unroll 4
        for (int c4 = 0; c4 < 16; ++c4) {
            float4 q[8];
#pragma unroll
            for (int k = 0; k < 8; ++k) q[k] = s_xq4[k][c4];
            const float* xb = poolb + (size_t)(c4 * 4) * POOL_P;
#pragma unroll
            for (int pi = 0; pi < 3; ++pi) {
                const int p = tid + pi * 256;
                if (p < POOL_P) {
                    float x0 = xb[p];
                    float x1 = xb[POOL_P + p];
                    float x2 = xb[2 * POOL_P + p];
                    float x3 = xb[3 * POOL_P + p];
#pragma unroll
                    for (int k = 0; k < 8; ++k) {
                        d[pi][k] = fmaf(x0, q[k].x, d[pi][k]);
                        d[pi][k] = fmaf(x1, q[k].y, d[pi][k]);
                        d[pi][k] = fmaf(x2, q[k].z, d[pi][k]);
                        d[pi][k] = fmaf(x3, q[k].w, d[pi][k]);
                    }
                }
            }
        }
#pragma unroll
        for (int pi = 0; pi < 3; ++pi) {
            const int p = tid + pi * 256;
            if (p < POOL_P) {
                const float ip = g_invn[b * POOL_P + p];
                const int pp = ph(p);
#pragma unroll
                for (int k = 0; k < 8; ++k)
                    s_cols[k][pp] = d[pi][k] * ip;
            }
        }
    }
    __syncthreads();

    // ---- register bitonic sort, i = lane*32 + r ---------------------------
    float val[32];
#pragma unroll
    for (int r = 0; r < 32; ++r)
        val[r] = (lane < 18) ? s_cols[w][lane * 32 + ((r ^ lane) & 31)]
                             : -FLT_MAX;

    bstep_reg<1,0>(val, lane);
    bstep_reg<2,1>(val, lane); bstep_reg<2,0>(val, lane);
    bstep_reg<3,2>(val, lane); bstep_reg<3,1>(val, lane); bstep_reg<3,0>(val, lane);
    bstep_reg<4,3>(val, lane); bstep_reg<4,2>(val, lane); bstep_reg<4,1>(val, lane); bstep_reg<4,0>(val, lane);
    bstep_reg<5,4>(val, lane); bstep_reg<5,3>(val, lane); bstep_reg<5,2>(val, lane); bstep_reg<5,1>(val, lane); bstep_reg<5,0>(val, lane);
    bstep_shfl<6,5>(val, lane);
    bstep_reg<6,4>(val, lane); bstep_reg<6,3>(val, lane); bstep_reg<6,2>(val, lane); bstep_reg<6,1>(val, lane); bstep_reg<6,0>(val, lane);
    bstep_shfl<7,6>(val, lane); bstep_shfl<7,5>(val, lane);
    bstep_reg<7,4>(val, lane); bstep_reg<7,3>(val, lane); bstep_reg<7,2>(val, lane); bstep_reg<7,1>(val, lane); bstep_reg<7,0>(val, lane);
    bstep_shfl<8,7>(val, lane); bstep_shfl<8,6>(val, lane); bstep_shfl<8,5>(val, lane);
    bstep_reg<8,4>(val, lane); bstep_reg<8,3>(val, lane); bstep_reg<8,2>(val, lane); bstep_reg<8,1>(val, lane); bstep_reg<8,0>(val, lane);
    bstep_shfl<9,8>(val, lane); bstep_shfl<9,7>(val, lane); bstep_shfl<9,6>(val, lane); bstep_shfl<9,5>(val, lane);
    bstep_reg<9,4>(val, lane); bstep_reg<9,3>(val, lane); bstep_reg<9,2>(val, lane); bstep_reg<9,1>(val, lane); bstep_reg<9,0>(val, lane);
    bstep_shfl<10,9>(val, lane); bstep_shfl<10,8>(val, lane); bstep_shfl<10,7>(val, lane); bstep_shfl<10,6>(val, lane); bstep_shfl<10,5>(val, lane);
    bstep_reg<10,4>(val, lane); bstep_reg<10,3>(val, lane); bstep_reg<10,2>(val, lane); bstep_reg<10,1>(val, lane); bstep_reg<10,0>(val, lane);

    if (lane < 18) {
#pragma unroll
        for (int r = 0; r < 32; ++r)
            s_cols[w][lane * 32 + ((r ^ lane) & 31)] = val[r];
    }
    __syncthreads();

    const double step = 574.0 / 114.0;   // np.linspace(1, 575, 115) step
    for (int idx = tid; idx < 8 * OUT_R; idx += 256) {
        int k = idx & 7, rr = idx >> 3;
        int rank = (int)rint(1.0 + (double)rr * step);  // half-even == np.round
        float invq = g_invn[b * POOL_P + q0 + k];
        out[((size_t)b * OUT_R + rr) * POOL_P + (q0 + k)] =
            s_cols[k][ph(rank)] * invq * (1.0f / 64.0f);
    }
}

// ---------------------------------------------------------------------------
extern "C" void kernel_launch(void* const* d_in, const int* in_sizes, int n_in,
                              void* d_out, int out_size)
{
    const float* x = (const float*)d_in[0];
    float* out = (float*)d_out;

    s1a_kernel<<<512 * 8, 128, S1A_SMEM_BYTES>>>(x);
    s1b_kernel<<<512, 256>>>();
    invn_kernel<<<(8 * POOL_P + 255) / 256, 256>>>();
    stage2_kernel<<<8 * 72, 256>>>(out);
}